// round 1
// baseline (speedup 1.0000x reference)
#include <cuda_runtime.h>
#include <math.h>

// Kabsch / Procrustes layer:
//   p_pred = p_src + cors
//   H[b]   = (p_src - c_src)^T (p_pred - c_pred)      (3x3)
//   r      = (polar_orthogonal_factor(H))^T            ( == v u^T from SVD)
//   t      = c_pred - r c_src
//   out[b] = [[r t],[0 0 0 1]]                          (4x4)
//
// Reduction phase: one CTA per batch, 256 threads, each handles 4 points via
// 3 aligned float4 loads per input array. 15 accumulators reduced via warp
// shuffles + shared atomics. Thread 0 finishes with a double-precision
// scaled Newton polar iteration (X <- 0.5*(mu X + mu^-1 X^-T)).

__global__ __launch_bounds__(256, 8)
void kabsch_kernel(const float* __restrict__ cors,
                   const float* __restrict__ src,
                   float* __restrict__ out,
                   int N)
{
    const int b   = blockIdx.x;
    const int tid = threadIdx.x;
    const size_t base = (size_t)b * N * 3;

    const float4* __restrict__ s4 = reinterpret_cast<const float4*>(src + base);
    const float4* __restrict__ c4 = reinterpret_cast<const float4*>(cors + base);

    // 15 accumulators: src sums (3), pred sums (3), cross products (9)
    float ssx = 0.f, ssy = 0.f, ssz = 0.f;
    float spx = 0.f, spy = 0.f, spz = 0.f;
    float h00 = 0.f, h01 = 0.f, h02 = 0.f;
    float h10 = 0.f, h11 = 0.f, h12 = 0.f;
    float h20 = 0.f, h21 = 0.f, h22 = 0.f;

    const int nf4 = (N * 3) / 4;                 // float4 count (768 for N=1024)
    // thread t owns float4 triples [3t, 3t+1, 3t+2], strided by 3*blockDim
    for (int f = tid * 3; f + 2 < nf4; f += blockDim.x * 3) {
        float a[12], c[12];
        float4 v;
        v = s4[f + 0]; a[0] = v.x; a[1] = v.y; a[2]  = v.z; a[3]  = v.w;
        v = s4[f + 1]; a[4] = v.x; a[5] = v.y; a[6]  = v.z; a[7]  = v.w;
        v = s4[f + 2]; a[8] = v.x; a[9] = v.y; a[10] = v.z; a[11] = v.w;
        v = c4[f + 0]; c[0] = v.x; c[1] = v.y; c[2]  = v.z; c[3]  = v.w;
        v = c4[f + 1]; c[4] = v.x; c[5] = v.y; c[6]  = v.z; c[7]  = v.w;
        v = c4[f + 2]; c[8] = v.x; c[9] = v.y; c[10] = v.z; c[11] = v.w;

        #pragma unroll
        for (int p = 0; p < 4; ++p) {
            const float sx = a[3*p + 0], sy = a[3*p + 1], sz = a[3*p + 2];
            const float px = sx + c[3*p + 0];
            const float py = sy + c[3*p + 1];
            const float pz = sz + c[3*p + 2];
            ssx += sx; ssy += sy; ssz += sz;
            spx += px; spy += py; spz += pz;
            h00 = fmaf(sx, px, h00); h01 = fmaf(sx, py, h01); h02 = fmaf(sx, pz, h02);
            h10 = fmaf(sy, px, h10); h11 = fmaf(sy, py, h11); h12 = fmaf(sy, pz, h12);
            h20 = fmaf(sz, px, h20); h21 = fmaf(sz, py, h21); h22 = fmaf(sz, pz, h22);
        }
    }

    // ---- warp reduction of 15 values ----
    float acc[15] = { ssx, ssy, ssz, spx, spy, spz,
                      h00, h01, h02, h10, h11, h12, h20, h21, h22 };
    #pragma unroll
    for (int off = 16; off > 0; off >>= 1) {
        #pragma unroll
        for (int k = 0; k < 15; ++k)
            acc[k] += __shfl_down_sync(0xFFFFFFFFu, acc[k], off);
    }

    __shared__ float s_acc[15];
    if (tid < 15) s_acc[tid] = 0.f;
    __syncthreads();
    if ((tid & 31) == 0) {
        #pragma unroll
        for (int k = 0; k < 15; ++k)
            atomicAdd(&s_acc[k], acc[k]);
    }
    __syncthreads();

    if (tid != 0) return;

    // ---- final 3x3 math in double ----
    const double iN = 1.0 / (double)N;
    double Ssrc[3]  = { s_acc[0], s_acc[1], s_acc[2] };
    double Spred[3] = { s_acc[3], s_acc[4], s_acc[5] };

    // H[i][j] = sum(src_i * pred_j) - Ssrc[i]*Spred[j]/N
    double X[9];
    #pragma unroll
    for (int i = 0; i < 3; ++i)
        #pragma unroll
        for (int j = 0; j < 3; ++j)
            X[i*3 + j] = (double)s_acc[6 + i*3 + j] - Ssrc[i] * Spred[j] * iN;

    // Scaled Newton iteration for the orthogonal polar factor W = u @ vh
    #pragma unroll 1
    for (int it = 0; it < 30; ++it) {
        double C[9];  // cofactor matrix: X^{-T} = C / det
        C[0] =  (X[4]*X[8] - X[5]*X[7]);
        C[1] = -(X[3]*X[8] - X[5]*X[6]);
        C[2] =  (X[3]*X[7] - X[4]*X[6]);
        C[3] = -(X[1]*X[8] - X[2]*X[7]);
        C[4] =  (X[0]*X[8] - X[2]*X[6]);
        C[5] = -(X[0]*X[7] - X[1]*X[6]);
        C[6] =  (X[1]*X[5] - X[2]*X[4]);
        C[7] = -(X[0]*X[5] - X[2]*X[3]);
        C[8] =  (X[0]*X[4] - X[1]*X[3]);
        const double det = X[0]*C[0] + X[1]*C[1] + X[2]*C[2];
        const double invdet = 1.0 / det;

        double nX = 0.0, nI = 0.0;
        double XiT[9];
        #pragma unroll
        for (int k = 0; k < 9; ++k) {
            XiT[k] = C[k] * invdet;
            nX += X[k]   * X[k];
            nI += XiT[k] * XiT[k];
        }
        // Higham Frobenius scaling: mu = (||X^-1||_F / ||X||_F)^(1/2)
        const double mu  = sqrt(sqrt(nI / nX));
        const double imu = 1.0 / mu;

        double diff = 0.0;
        #pragma unroll
        for (int k = 0; k < 9; ++k) {
            const double xn = 0.5 * (mu * X[k] + imu * XiT[k]);
            const double d  = xn - X[k];
            diff += d * d;
            X[k] = xn;
        }
        if (diff < 1e-26 * nX) break;
    }

    // r = W^T ; t = c_pred - r * c_src
    const double csx = Ssrc[0]*iN,  csy = Ssrc[1]*iN,  csz = Ssrc[2]*iN;
    const double cpx = Spred[0]*iN, cpy = Spred[1]*iN, cpz = Spred[2]*iN;

    double r[3][3];
    #pragma unroll
    for (int i = 0; i < 3; ++i)
        #pragma unroll
        for (int j = 0; j < 3; ++j)
            r[i][j] = X[j*3 + i];

    const double t0 = cpx - (r[0][0]*csx + r[0][1]*csy + r[0][2]*csz);
    const double t1 = cpy - (r[1][0]*csx + r[1][1]*csy + r[1][2]*csz);
    const double t2 = cpz - (r[2][0]*csx + r[2][1]*csy + r[2][2]*csz);

    float* o = out + (size_t)b * 16;
    o[0]  = (float)r[0][0]; o[1]  = (float)r[0][1]; o[2]  = (float)r[0][2]; o[3]  = (float)t0;
    o[4]  = (float)r[1][0]; o[5]  = (float)r[1][1]; o[6]  = (float)r[1][2]; o[7]  = (float)t1;
    o[8]  = (float)r[2][0]; o[9]  = (float)r[2][1]; o[10] = (float)r[2][2]; o[11] = (float)t2;
    o[12] = 0.f; o[13] = 0.f; o[14] = 0.f; o[15] = 1.f;
}

extern "C" void kernel_launch(void* const* d_in, const int* in_sizes, int n_in,
                              void* d_out, int out_size)
{
    const float* cors = (const float*)d_in[0];
    const float* src  = (const float*)d_in[1];
    float* out        = (float*)d_out;

    const int B = out_size / 16;
    const int N = in_sizes[0] / (3 * B);

    kabsch_kernel<<<B, 256>>>(cors, src, out, N);
}

// round 2
// speedup vs baseline: 5.8282x; 5.8282x over previous
#include <cuda_runtime.h>
#include <math.h>

// Two-phase Kabsch / Procrustes:
//   Phase A (memory-bound): per-batch reduction of 1024 points -> 15 scalars
//     (3 src sums, 3 pred sums, 9 cross-products sum(src_i*pred_j)).
//   Phase B (tiny, parallel): one thread per batch forms H and runs a scaled
//     Newton polar iteration in fp32 to get W = u@vh, then r = W^T, t, 4x4 out.
//
// Phase A writes SoA scratch g_scr[k*BMAX + b] so Phase B reads coalesced.

#define BMAX 8192

__device__ float g_scr[15 * BMAX];

__global__ __launch_bounds__(256, 4)
void reduce_kernel(const float* __restrict__ cors,
                   const float* __restrict__ src,
                   int N, int B)
{
    const int b   = blockIdx.x;
    const int tid = threadIdx.x;
    const size_t base = (size_t)b * N * 3;

    const float4* __restrict__ s4 = reinterpret_cast<const float4*>(src + base);
    const float4* __restrict__ c4 = reinterpret_cast<const float4*>(cors + base);

    float ssx = 0.f, ssy = 0.f, ssz = 0.f;
    float spx = 0.f, spy = 0.f, spz = 0.f;
    float h00 = 0.f, h01 = 0.f, h02 = 0.f;
    float h10 = 0.f, h11 = 0.f, h12 = 0.f;
    float h20 = 0.f, h21 = 0.f, h22 = 0.f;

    const int nf4 = (N * 3) / 4;   // 768 for N=1024 -> exactly one pass at 256 thr
    for (int f = tid * 3; f + 2 < nf4; f += blockDim.x * 3) {
        float a[12], c[12];
        float4 v;
        v = s4[f + 0]; a[0] = v.x; a[1] = v.y; a[2]  = v.z; a[3]  = v.w;
        v = s4[f + 1]; a[4] = v.x; a[5] = v.y; a[6]  = v.z; a[7]  = v.w;
        v = s4[f + 2]; a[8] = v.x; a[9] = v.y; a[10] = v.z; a[11] = v.w;
        v = c4[f + 0]; c[0] = v.x; c[1] = v.y; c[2]  = v.z; c[3]  = v.w;
        v = c4[f + 1]; c[4] = v.x; c[5] = v.y; c[6]  = v.z; c[7]  = v.w;
        v = c4[f + 2]; c[8] = v.x; c[9] = v.y; c[10] = v.z; c[11] = v.w;

        #pragma unroll
        for (int p = 0; p < 4; ++p) {
            const float sx = a[3*p + 0], sy = a[3*p + 1], sz = a[3*p + 2];
            const float px = sx + c[3*p + 0];
            const float py = sy + c[3*p + 1];
            const float pz = sz + c[3*p + 2];
            ssx += sx; ssy += sy; ssz += sz;
            spx += px; spy += py; spz += pz;
            h00 = fmaf(sx, px, h00); h01 = fmaf(sx, py, h01); h02 = fmaf(sx, pz, h02);
            h10 = fmaf(sy, px, h10); h11 = fmaf(sy, py, h11); h12 = fmaf(sy, pz, h12);
            h20 = fmaf(sz, px, h20); h21 = fmaf(sz, py, h21); h22 = fmaf(sz, pz, h22);
        }
    }

    float acc[15] = { ssx, ssy, ssz, spx, spy, spz,
                      h00, h01, h02, h10, h11, h12, h20, h21, h22 };
    #pragma unroll
    for (int off = 16; off > 0; off >>= 1) {
        #pragma unroll
        for (int k = 0; k < 15; ++k)
            acc[k] += __shfl_down_sync(0xFFFFFFFFu, acc[k], off);
    }

    __shared__ float s_acc[15];
    if (tid < 15) s_acc[tid] = 0.f;
    __syncthreads();
    if ((tid & 31) == 0) {
        #pragma unroll
        for (int k = 0; k < 15; ++k)
            atomicAdd(&s_acc[k], acc[k]);
    }
    __syncthreads();

    if (tid < 15) g_scr[tid * BMAX + b] = s_acc[tid];
}

// One thread per batch: fp32 scaled-Newton polar factor of H, emit 4x4.
__global__ void solve_kernel(float* __restrict__ out, int N, int B)
{
    const int b = blockIdx.x * blockDim.x + threadIdx.x;
    if (b >= B) return;

    float a[15];
    #pragma unroll
    for (int k = 0; k < 15; ++k) a[k] = g_scr[k * BMAX + b];

    const float iN = 1.0f / (float)N;
    const float csx = a[0] * iN, csy = a[1] * iN, csz = a[2] * iN;   // src centroid
    const float cpx = a[3] * iN, cpy = a[4] * iN, cpz = a[5] * iN;   // pred centroid

    // H[i][j] = sum(src_i * pred_j) - N * cs_i * cp_j
    float X[9];
    const float cs[3] = { csx, csy, csz }, cp[3] = { cpx, cpy, cpz };
    #pragma unroll
    for (int i = 0; i < 3; ++i)
        #pragma unroll
        for (int j = 0; j < 3; ++j)
            X[i*3 + j] = a[6 + i*3 + j] - (float)N * cs[i] * cp[j];

    // Scaled Newton iteration: X <- 0.5*(mu X + mu^-1 X^-T); converges to u@vh.
    #pragma unroll 1
    for (int it = 0; it < 12; ++it) {
        float C0 =  (X[4]*X[8] - X[5]*X[7]);
        float C1 = -(X[3]*X[8] - X[5]*X[6]);
        float C2 =  (X[3]*X[7] - X[4]*X[6]);
        float C3 = -(X[1]*X[8] - X[2]*X[7]);
        float C4 =  (X[0]*X[8] - X[2]*X[6]);
        float C5 = -(X[0]*X[7] - X[1]*X[6]);
        float C6 =  (X[1]*X[5] - X[2]*X[4]);
        float C7 = -(X[0]*X[5] - X[2]*X[3]);
        float C8 =  (X[0]*X[4] - X[1]*X[3]);
        const float det    = X[0]*C0 + X[1]*C1 + X[2]*C2;
        const float invdet = 1.0f / det;

        float XiT[9] = { C0*invdet, C1*invdet, C2*invdet,
                         C3*invdet, C4*invdet, C5*invdet,
                         C6*invdet, C7*invdet, C8*invdet };

        float nX = 0.f, nI = 0.f;
        #pragma unroll
        for (int k = 0; k < 9; ++k) { nX += X[k]*X[k]; nI += XiT[k]*XiT[k]; }

        // Higham Frobenius scaling: mu = (||X^-1||_F / ||X||_F)^(1/2)
        const float mu  = sqrtf(sqrtf(nI / nX));
        const float imu = 1.0f / mu;

        #pragma unroll
        for (int k = 0; k < 9; ++k)
            X[k] = 0.5f * (mu * X[k] + imu * XiT[k]);
    }

    // r = W^T ; t = c_pred - r * c_src
    float r00 = X[0], r01 = X[3], r02 = X[6];
    float r10 = X[1], r11 = X[4], r12 = X[7];
    float r20 = X[2], r21 = X[5], r22 = X[8];

    const float t0 = cpx - (r00*csx + r01*csy + r02*csz);
    const float t1 = cpy - (r10*csx + r11*csy + r12*csz);
    const float t2 = cpz - (r20*csx + r21*csy + r22*csz);

    float4* o4 = reinterpret_cast<float4*>(out + (size_t)b * 16);
    o4[0] = make_float4(r00, r01, r02, t0);
    o4[1] = make_float4(r10, r11, r12, t1);
    o4[2] = make_float4(r20, r21, r22, t2);
    o4[3] = make_float4(0.f, 0.f, 0.f, 1.f);
}

extern "C" void kernel_launch(void* const* d_in, const int* in_sizes, int n_in,
                              void* d_out, int out_size)
{
    const float* cors = (const float*)d_in[0];
    const float* src  = (const float*)d_in[1];
    float* out        = (float*)d_out;

    const int B = out_size / 16;
    const int N = in_sizes[0] / (3 * B);

    reduce_kernel<<<B, 256>>>(cors, src, N, B);
    solve_kernel<<<(B + 255) / 256, 256>>>(out, N, B);
}

// round 3
// speedup vs baseline: 6.3045x; 1.0817x over previous
#include <cuda_runtime.h>
#include <math.h>

// Fused Kabsch / Procrustes: one CTA per batch.
//   1) 256 threads reduce 1024 points -> 15 scalars
//      (3 src sums, 3 pred sums, 9 cross-products sum(src_i*pred_j))
//   2) thread 0 forms H and runs an fp32 scaled-Newton polar iteration
//      (X <- 0.5*(mu X + mu^-1 X^-T)) converging to W = u@vh, then emits
//      r = W^T, t = c_pred - r c_src, as a 4x4 row-major transform.
// The per-block serial solve (~1.5k cycles on 1 thread) hides behind other
// resident blocks' memory phases.

__global__ __launch_bounds__(256, 5)
void kabsch_fused(const float* __restrict__ cors,
                  const float* __restrict__ src,
                  float* __restrict__ out,
                  int N)
{
    const int b    = blockIdx.x;
    const int tid  = threadIdx.x;
    const int lane = tid & 31;
    const int wid  = tid >> 5;
    const size_t base = (size_t)b * N * 3;

    const float4* __restrict__ s4 = reinterpret_cast<const float4*>(src + base);
    const float4* __restrict__ c4 = reinterpret_cast<const float4*>(cors + base);

    float ssx = 0.f, ssy = 0.f, ssz = 0.f;
    float spx = 0.f, spy = 0.f, spz = 0.f;
    float h00 = 0.f, h01 = 0.f, h02 = 0.f;
    float h10 = 0.f, h11 = 0.f, h12 = 0.f;
    float h20 = 0.f, h21 = 0.f, h22 = 0.f;

    const int nf4 = (N * 3) / 4;   // 768 for N=1024 -> one pass at 256 threads
    for (int f = tid * 3; f + 2 < nf4; f += blockDim.x * 3) {
        float a[12], c[12];
        float4 v;
        v = s4[f + 0]; a[0] = v.x; a[1] = v.y; a[2]  = v.z; a[3]  = v.w;
        v = s4[f + 1]; a[4] = v.x; a[5] = v.y; a[6]  = v.z; a[7]  = v.w;
        v = s4[f + 2]; a[8] = v.x; a[9] = v.y; a[10] = v.z; a[11] = v.w;
        v = c4[f + 0]; c[0] = v.x; c[1] = v.y; c[2]  = v.z; c[3]  = v.w;
        v = c4[f + 1]; c[4] = v.x; c[5] = v.y; c[6]  = v.z; c[7]  = v.w;
        v = c4[f + 2]; c[8] = v.x; c[9] = v.y; c[10] = v.z; c[11] = v.w;

        #pragma unroll
        for (int p = 0; p < 4; ++p) {
            const float sx = a[3*p + 0], sy = a[3*p + 1], sz = a[3*p + 2];
            const float px = sx + c[3*p + 0];
            const float py = sy + c[3*p + 1];
            const float pz = sz + c[3*p + 2];
            ssx += sx; ssy += sy; ssz += sz;
            spx += px; spy += py; spz += pz;
            h00 = fmaf(sx, px, h00); h01 = fmaf(sx, py, h01); h02 = fmaf(sx, pz, h02);
            h10 = fmaf(sy, px, h10); h11 = fmaf(sy, py, h11); h12 = fmaf(sy, pz, h12);
            h20 = fmaf(sz, px, h20); h21 = fmaf(sz, py, h21); h22 = fmaf(sz, pz, h22);
        }
    }

    // ---- warp-level reduction of the 15 accumulators ----
    float acc[15] = { ssx, ssy, ssz, spx, spy, spz,
                      h00, h01, h02, h10, h11, h12, h20, h21, h22 };
    #pragma unroll
    for (int off = 16; off > 0; off >>= 1) {
        #pragma unroll
        for (int k = 0; k < 15; ++k)
            acc[k] += __shfl_down_sync(0xFFFFFFFFu, acc[k], off);
    }

    // ---- cross-warp: 8 warps x 15 values in smem, warp 0 finishes ----
    __shared__ float s_part[8][15];
    if (lane == 0) {
        #pragma unroll
        for (int k = 0; k < 15; ++k) s_part[wid][k] = acc[k];
    }
    __syncthreads();

    if (tid != 0) return;

    float a[15];
    #pragma unroll
    for (int k = 0; k < 15; ++k) {
        float s = s_part[0][k];
        #pragma unroll
        for (int w = 1; w < 8; ++w) s += s_part[w][k];
        a[k] = s;
    }

    // ---- thread 0: fp32 polar decomposition of H ----
    const float iN = 1.0f / (float)N;
    const float cs[3] = { a[0]*iN, a[1]*iN, a[2]*iN };   // src centroid
    const float cp[3] = { a[3]*iN, a[4]*iN, a[5]*iN };   // pred centroid

    // H[i][j] = sum(src_i * pred_j) - N * cs_i * cp_j
    float X[9];
    #pragma unroll
    for (int i = 0; i < 3; ++i)
        #pragma unroll
        for (int j = 0; j < 3; ++j)
            X[i*3 + j] = a[6 + i*3 + j] - (float)N * cs[i] * cp[j];

    // Scaled Newton iteration -> orthogonal polar factor W = u@vh
    #pragma unroll 1
    for (int it = 0; it < 10; ++it) {
        const float C0 =  (X[4]*X[8] - X[5]*X[7]);
        const float C1 = -(X[3]*X[8] - X[5]*X[6]);
        const float C2 =  (X[3]*X[7] - X[4]*X[6]);
        const float C3 = -(X[1]*X[8] - X[2]*X[7]);
        const float C4 =  (X[0]*X[8] - X[2]*X[6]);
        const float C5 = -(X[0]*X[7] - X[1]*X[6]);
        const float C6 =  (X[1]*X[5] - X[2]*X[4]);
        const float C7 = -(X[0]*X[5] - X[2]*X[3]);
        const float C8 =  (X[0]*X[4] - X[1]*X[3]);
        const float det    = X[0]*C0 + X[1]*C1 + X[2]*C2;
        const float invdet = 1.0f / det;

        float XiT[9] = { C0*invdet, C1*invdet, C2*invdet,
                         C3*invdet, C4*invdet, C5*invdet,
                         C6*invdet, C7*invdet, C8*invdet };

        float nX = 0.f, nI = 0.f;
        #pragma unroll
        for (int k = 0; k < 9; ++k) { nX += X[k]*X[k]; nI += XiT[k]*XiT[k]; }

        // Higham Frobenius scaling: mu = (||X^-1||_F / ||X||_F)^(1/2)
        const float mu  = sqrtf(sqrtf(nI / nX));
        const float imu = 1.0f / mu;

        #pragma unroll
        for (int k = 0; k < 9; ++k)
            X[k] = 0.5f * (mu * X[k] + imu * XiT[k]);
    }

    // r = W^T ; t = c_pred - r * c_src
    const float r00 = X[0], r01 = X[3], r02 = X[6];
    const float r10 = X[1], r11 = X[4], r12 = X[7];
    const float r20 = X[2], r21 = X[5], r22 = X[8];

    const float t0 = cp[0] - (r00*cs[0] + r01*cs[1] + r02*cs[2]);
    const float t1 = cp[1] - (r10*cs[0] + r11*cs[1] + r12*cs[2]);
    const float t2 = cp[2] - (r20*cs[0] + r21*cs[1] + r22*cs[2]);

    float4* o4 = reinterpret_cast<float4*>(out + (size_t)b * 16);
    o4[0] = make_float4(r00, r01, r02, t0);
    o4[1] = make_float4(r10, r11, r12, t1);
    o4[2] = make_float4(r20, r21, r22, t2);
    o4[3] = make_float4(0.f, 0.f, 0.f, 1.f);
}

extern "C" void kernel_launch(void* const* d_in, const int* in_sizes, int n_in,
                              void* d_out, int out_size)
{
    const float* cors = (const float*)d_in[0];
    const float* src  = (const float*)d_in[1];
    float* out        = (float*)d_out;

    const int B = out_size / 16;
    const int N = in_sizes[0] / (3 * B);

    kabsch_fused<<<B, 256>>>(cors, src, out, N);
}

// round 5
// speedup vs baseline: 7.6517x; 1.2137x over previous
#include <cuda_runtime.h>
#include <math.h>

// Two-phase Kabsch / Procrustes, streaming-optimized.
//
// Kernel A (pure streaming): one CTA per batch, 256 threads, each thread does
//   6x LDG.128 (streaming hint) and accumulates 15 values (3 src sums, 3 pred
//   sums, 9 cross products). Per-warp shuffle reduction, lane 0 writes a 64B
//   record. No smem, no __syncthreads, no serial tail -> blocks retire as
//   soon as their loads complete.
//
// Kernel B (tiny): one thread per batch sums the 8 warp records (L2-hot),
//   forms H, runs an fp32 scaled-Newton polar iteration (fast-math divides)
//   to get W = u@vh, emits [[W^T, t],[0 0 0 1]].

#define BMAX 8192
__device__ float g_scr[BMAX * 8 * 16];   // [batch][warp][16] (15 used + pad)

__global__ __launch_bounds__(256, 5)
void reduce_kernel(const float* __restrict__ cors,
                   const float* __restrict__ src,
                   int N)
{
    const int b    = blockIdx.x;
    const int tid  = threadIdx.x;
    const int lane = tid & 31;
    const int wid  = tid >> 5;
    const size_t base = (size_t)b * N * 3;

    const float4* __restrict__ s4 = reinterpret_cast<const float4*>(src + base);
    const float4* __restrict__ c4 = reinterpret_cast<const float4*>(cors + base);

    float acc[15];
    #pragma unroll
    for (int k = 0; k < 15; ++k) acc[k] = 0.f;
    // acc: [0..2] src sums, [3..5] pred sums, [6..14] H row-major

    const int nf4 = (N * 3) / 4;   // 768 for N=1024 -> one pass at 256 threads
    for (int f = tid * 3; f + 2 < nf4; f += blockDim.x * 3) {
        float a[12], c[12];
        float4 v;
        v = __ldcs(&s4[f + 0]); a[0] = v.x; a[1] = v.y; a[2]  = v.z; a[3]  = v.w;
        v = __ldcs(&s4[f + 1]); a[4] = v.x; a[5] = v.y; a[6]  = v.z; a[7]  = v.w;
        v = __ldcs(&s4[f + 2]); a[8] = v.x; a[9] = v.y; a[10] = v.z; a[11] = v.w;
        v = __ldcs(&c4[f + 0]); c[0] = v.x; c[1] = v.y; c[2]  = v.z; c[3]  = v.w;
        v = __ldcs(&c4[f + 1]); c[4] = v.x; c[5] = v.y; c[6]  = v.z; c[7]  = v.w;
        v = __ldcs(&c4[f + 2]); c[8] = v.x; c[9] = v.y; c[10] = v.z; c[11] = v.w;

        #pragma unroll
        for (int p = 0; p < 4; ++p) {
            const float sx = a[3*p + 0], sy = a[3*p + 1], sz = a[3*p + 2];
            const float px = sx + c[3*p + 0];
            const float py = sy + c[3*p + 1];
            const float pz = sz + c[3*p + 2];
            acc[0] += sx; acc[1] += sy; acc[2] += sz;
            acc[3] += px; acc[4] += py; acc[5] += pz;
            acc[6]  = fmaf(sx, px, acc[6]);  acc[7]  = fmaf(sx, py, acc[7]);  acc[8]  = fmaf(sx, pz, acc[8]);
            acc[9]  = fmaf(sy, px, acc[9]);  acc[10] = fmaf(sy, py, acc[10]); acc[11] = fmaf(sy, pz, acc[11]);
            acc[12] = fmaf(sz, px, acc[12]); acc[13] = fmaf(sz, py, acc[13]); acc[14] = fmaf(sz, pz, acc[14]);
        }
    }

    // per-warp shuffle reduction of the 15 accumulators
    #pragma unroll
    for (int off = 16; off > 0; off >>= 1) {
        #pragma unroll
        for (int k = 0; k < 15; ++k)
            acc[k] += __shfl_down_sync(0xFFFFFFFFu, acc[k], off);
    }

    if (lane == 0) {
        float4* rec = reinterpret_cast<float4*>(g_scr + ((size_t)b * 8 + wid) * 16);
        rec[0] = make_float4(acc[0],  acc[1],  acc[2],  acc[3]);
        rec[1] = make_float4(acc[4],  acc[5],  acc[6],  acc[7]);
        rec[2] = make_float4(acc[8],  acc[9],  acc[10], acc[11]);
        rec[3] = make_float4(acc[12], acc[13], acc[14], 0.f);
    }
}

// One thread per batch: sum warp records, fp32 polar factor of H, emit 4x4.
__global__ __launch_bounds__(128)
void solve_kernel(float* __restrict__ out, int N, int B)
{
    const int b = blockIdx.x * blockDim.x + threadIdx.x;
    if (b >= B) return;

    float a[15];
    #pragma unroll
    for (int k = 0; k < 15; ++k) a[k] = 0.f;

    const float4* rec = reinterpret_cast<const float4*>(g_scr + (size_t)b * 8 * 16);
    #pragma unroll
    for (int w = 0; w < 8; ++w) {
        float4 r0 = rec[w*4 + 0], r1 = rec[w*4 + 1], r2 = rec[w*4 + 2], r3 = rec[w*4 + 3];
        a[0]  += r0.x; a[1]  += r0.y; a[2]  += r0.z; a[3]  += r0.w;
        a[4]  += r1.x; a[5]  += r1.y; a[6]  += r1.z; a[7]  += r1.w;
        a[8]  += r2.x; a[9]  += r2.y; a[10] += r2.z; a[11] += r2.w;
        a[12] += r3.x; a[13] += r3.y; a[14] += r3.z;
    }

    const float iN = 1.0f / (float)N;
    const float cs[3] = { a[0]*iN, a[1]*iN, a[2]*iN };   // src centroid
    const float cp[3] = { a[3]*iN, a[4]*iN, a[5]*iN };   // pred centroid

    // H[i][j] = sum(src_i * pred_j) - N * cs_i * cp_j
    float X[9];
    #pragma unroll
    for (int i = 0; i < 3; ++i)
        #pragma unroll
        for (int j = 0; j < 3; ++j)
            X[i*3 + j] = a[6 + i*3 + j] - (float)N * cs[i] * cp[j];

    // Scaled Newton iteration -> orthogonal polar factor W = u@vh
    #pragma unroll 1
    for (int it = 0; it < 8; ++it) {
        const float C0 =  (X[4]*X[8] - X[5]*X[7]);
        const float C1 = -(X[3]*X[8] - X[5]*X[6]);
        const float C2 =  (X[3]*X[7] - X[4]*X[6]);
        const float C3 = -(X[1]*X[8] - X[2]*X[7]);
        const float C4 =  (X[0]*X[8] - X[2]*X[6]);
        const float C5 = -(X[0]*X[7] - X[1]*X[6]);
        const float C6 =  (X[1]*X[5] - X[2]*X[4]);
        const float C7 = -(X[0]*X[5] - X[2]*X[3]);
        const float C8 =  (X[0]*X[4] - X[1]*X[3]);
        const float det    = X[0]*C0 + X[1]*C1 + X[2]*C2;
        const float invdet = __fdividef(1.0f, det);

        float XiT[9] = { C0*invdet, C1*invdet, C2*invdet,
                         C3*invdet, C4*invdet, C5*invdet,
                         C6*invdet, C7*invdet, C8*invdet };

        float nX = 0.f, nI = 0.f;
        #pragma unroll
        for (int k = 0; k < 9; ++k) { nX += X[k]*X[k]; nI += XiT[k]*XiT[k]; }

        // Higham Frobenius scaling: mu = (||X^-1||_F / ||X||_F)^(1/2)
        const float mu  = sqrtf(sqrtf(__fdividef(nI, nX)));
        const float imu = sqrtf(sqrtf(__fdividef(nX, nI)));

        #pragma unroll
        for (int k = 0; k < 9; ++k)
            X[k] = 0.5f * (mu * X[k] + imu * XiT[k]);
    }

    // r = W^T ; t = c_pred - r * c_src
    const float r00 = X[0], r01 = X[3], r02 = X[6];
    const float r10 = X[1], r11 = X[4], r12 = X[7];
    const float r20 = X[2], r21 = X[5], r22 = X[8];

    const float t0 = cp[0] - (r00*cs[0] + r01*cs[1] + r02*cs[2]);
    const float t1 = cp[1] - (r10*cs[0] + r11*cs[1] + r12*cs[2]);
    const float t2 = cp[2] - (r20*cs[0] + r21*cs[1] + r22*cs[2]);

    float4* o4 = reinterpret_cast<float4*>(out + (size_t)b * 16);
    o4[0] = make_float4(r00, r01, r02, t0);
    o4[1] = make_float4(r10, r11, r12, t1);
    o4[2] = make_float4(r20, r21, r22, t2);
    o4[3] = make_float4(0.f, 0.f, 0.f, 1.f);
}

extern "C" void kernel_launch(void* const* d_in, const int* in_sizes, int n_in,
                              void* d_out, int out_size)
{
    const float* cors = (const float*)d_in[0];
    const float* src  = (const float*)d_in[1];
    float* out        = (float*)d_out;

    const int B = out_size / 16;
    const int N = in_sizes[0] / (3 * B);

    reduce_kernel<<<B, 256>>>(cors, src, N);
    solve_kernel<<<(B + 127) / 128, 128>>>(out, N, B);
}

// round 6
// speedup vs baseline: 7.7339x; 1.0107x over previous
#include <cuda_runtime.h>
#include <math.h>

// Two-phase Kabsch / Procrustes, streaming-optimized.
//
// Kernel A (pure streaming): one CTA per batch, 256 threads, each thread does
//   6x LDG.128 (streaming hint) and accumulates 15 values (3 src sums, 3 pred
//   sums, 9 cross products). Per-warp shuffle reduction, lane 0 writes a 64B
//   record. No smem, no __syncthreads, no serial tail -> blocks retire as
//   soon as their loads complete.
//
// Kernel B (tiny, latency-bound): one thread per batch, spread as 32-thread
//   blocks across many SMs. Sums the 8 warp records (L2-hot), forms H, runs
//   a 6-iteration fp32 scaled-Newton polar iteration (fast-math divides)
//   to get W = u@vh, emits [[W^T, t],[0 0 0 1]].

#define BMAX 8192
__device__ float g_scr[BMAX * 8 * 16];   // [batch][warp][16] (15 used + pad)

__global__ __launch_bounds__(256, 5)
void reduce_kernel(const float* __restrict__ cors,
                   const float* __restrict__ src,
                   int N)
{
    const int b    = blockIdx.x;
    const int tid  = threadIdx.x;
    const int lane = tid & 31;
    const int wid  = tid >> 5;
    const size_t base = (size_t)b * N * 3;

    const float4* __restrict__ s4 = reinterpret_cast<const float4*>(src + base);
    const float4* __restrict__ c4 = reinterpret_cast<const float4*>(cors + base);

    float acc[15];
    #pragma unroll
    for (int k = 0; k < 15; ++k) acc[k] = 0.f;
    // acc: [0..2] src sums, [3..5] pred sums, [6..14] H row-major

    const int nf4 = (N * 3) / 4;   // 768 for N=1024 -> one pass at 256 threads
    for (int f = tid * 3; f + 2 < nf4; f += blockDim.x * 3) {
        float a[12], c[12];
        float4 v;
        v = __ldcs(&s4[f + 0]); a[0] = v.x; a[1] = v.y; a[2]  = v.z; a[3]  = v.w;
        v = __ldcs(&s4[f + 1]); a[4] = v.x; a[5] = v.y; a[6]  = v.z; a[7]  = v.w;
        v = __ldcs(&s4[f + 2]); a[8] = v.x; a[9] = v.y; a[10] = v.z; a[11] = v.w;
        v = __ldcs(&c4[f + 0]); c[0] = v.x; c[1] = v.y; c[2]  = v.z; c[3]  = v.w;
        v = __ldcs(&c4[f + 1]); c[4] = v.x; c[5] = v.y; c[6]  = v.z; c[7]  = v.w;
        v = __ldcs(&c4[f + 2]); c[8] = v.x; c[9] = v.y; c[10] = v.z; c[11] = v.w;

        #pragma unroll
        for (int p = 0; p < 4; ++p) {
            const float sx = a[3*p + 0], sy = a[3*p + 1], sz = a[3*p + 2];
            const float px = sx + c[3*p + 0];
            const float py = sy + c[3*p + 1];
            const float pz = sz + c[3*p + 2];
            acc[0] += sx; acc[1] += sy; acc[2] += sz;
            acc[3] += px; acc[4] += py; acc[5] += pz;
            acc[6]  = fmaf(sx, px, acc[6]);  acc[7]  = fmaf(sx, py, acc[7]);  acc[8]  = fmaf(sx, pz, acc[8]);
            acc[9]  = fmaf(sy, px, acc[9]);  acc[10] = fmaf(sy, py, acc[10]); acc[11] = fmaf(sy, pz, acc[11]);
            acc[12] = fmaf(sz, px, acc[12]); acc[13] = fmaf(sz, py, acc[13]); acc[14] = fmaf(sz, pz, acc[14]);
        }
    }

    // per-warp shuffle reduction of the 15 accumulators
    #pragma unroll
    for (int off = 16; off > 0; off >>= 1) {
        #pragma unroll
        for (int k = 0; k < 15; ++k)
            acc[k] += __shfl_down_sync(0xFFFFFFFFu, acc[k], off);
    }

    if (lane == 0) {
        float4* rec = reinterpret_cast<float4*>(g_scr + ((size_t)b * 8 + wid) * 16);
        rec[0] = make_float4(acc[0],  acc[1],  acc[2],  acc[3]);
        rec[1] = make_float4(acc[4],  acc[5],  acc[6],  acc[7]);
        rec[2] = make_float4(acc[8],  acc[9],  acc[10], acc[11]);
        rec[3] = make_float4(acc[12], acc[13], acc[14], 0.f);
    }
}

// One thread per batch, 32-thread blocks spread across SMs.
__global__ __launch_bounds__(32)
void solve_kernel(float* __restrict__ out, int N, int B)
{
    const int b = blockIdx.x * blockDim.x + threadIdx.x;
    if (b >= B) return;

    float a[15];
    #pragma unroll
    for (int k = 0; k < 15; ++k) a[k] = 0.f;

    const float4* rec = reinterpret_cast<const float4*>(g_scr + (size_t)b * 8 * 16);
    #pragma unroll
    for (int w = 0; w < 8; ++w) {
        float4 r0 = rec[w*4 + 0], r1 = rec[w*4 + 1], r2 = rec[w*4 + 2], r3 = rec[w*4 + 3];
        a[0]  += r0.x; a[1]  += r0.y; a[2]  += r0.z; a[3]  += r0.w;
        a[4]  += r1.x; a[5]  += r1.y; a[6]  += r1.z; a[7]  += r1.w;
        a[8]  += r2.x; a[9]  += r2.y; a[10] += r2.z; a[11] += r2.w;
        a[12] += r3.x; a[13] += r3.y; a[14] += r3.z;
    }

    const float iN = 1.0f / (float)N;
    const float cs[3] = { a[0]*iN, a[1]*iN, a[2]*iN };   // src centroid
    const float cp[3] = { a[3]*iN, a[4]*iN, a[5]*iN };   // pred centroid

    // H[i][j] = sum(src_i * pred_j) - N * cs_i * cp_j
    float X[9];
    #pragma unroll
    for (int i = 0; i < 3; ++i)
        #pragma unroll
        for (int j = 0; j < 3; ++j)
            X[i*3 + j] = a[6 + i*3 + j] - (float)N * cs[i] * cp[j];

    // Scaled Newton iteration -> orthogonal polar factor W = u@vh
    #pragma unroll 1
    for (int it = 0; it < 6; ++it) {
        const float C0 =  (X[4]*X[8] - X[5]*X[7]);
        const float C1 = -(X[3]*X[8] - X[5]*X[6]);
        const float C2 =  (X[3]*X[7] - X[4]*X[6]);
        const float C3 = -(X[1]*X[8] - X[2]*X[7]);
        const float C4 =  (X[0]*X[8] - X[2]*X[6]);
        const float C5 = -(X[0]*X[7] - X[1]*X[6]);
        const float C6 =  (X[1]*X[5] - X[2]*X[4]);
        const float C7 = -(X[0]*X[5] - X[2]*X[3]);
        const float C8 =  (X[0]*X[4] - X[1]*X[3]);
        const float det    = X[0]*C0 + X[1]*C1 + X[2]*C2;
        const float invdet = __fdividef(1.0f, det);

        float XiT[9] = { C0*invdet, C1*invdet, C2*invdet,
                         C3*invdet, C4*invdet, C5*invdet,
                         C6*invdet, C7*invdet, C8*invdet };

        float nX = 0.f, nI = 0.f;
        #pragma unroll
        for (int k = 0; k < 9; ++k) { nX += X[k]*X[k]; nI += XiT[k]*XiT[k]; }

        // Higham Frobenius scaling: mu = (||X^-1||_F / ||X||_F)^(1/2)
        const float mu  = sqrtf(sqrtf(__fdividef(nI, nX)));
        const float imu = sqrtf(sqrtf(__fdividef(nX, nI)));

        #pragma unroll
        for (int k = 0; k < 9; ++k)
            X[k] = 0.5f * (mu * X[k] + imu * XiT[k]);
    }

    // r = W^T ; t = c_pred - r * c_src
    const float r00 = X[0], r01 = X[3], r02 = X[6];
    const float r10 = X[1], r11 = X[4], r12 = X[7];
    const float r20 = X[2], r21 = X[5], r22 = X[8];

    const float t0 = cp[0] - (r00*cs[0] + r01*cs[1] + r02*cs[2]);
    const float t1 = cp[1] - (r10*cs[0] + r11*cs[1] + r12*cs[2]);
    const float t2 = cp[2] - (r20*cs[0] + r21*cs[1] + r22*cs[2]);

    float4* o4 = reinterpret_cast<float4*>(out + (size_t)b * 16);
    o4[0] = make_float4(r00, r01, r02, t0);
    o4[1] = make_float4(r10, r11, r12, t1);
    o4[2] = make_float4(r20, r21, r22, t2);
    o4[3] = make_float4(0.f, 0.f, 0.f, 1.f);
}

extern "C" void kernel_launch(void* const* d_in, const int* in_sizes, int n_in,
                              void* d_out, int out_size)
{
    const float* cors = (const float*)d_in[0];
    const float* src  = (const float*)d_in[1];
    float* out        = (float*)d_out;

    const int B = out_size / 16;
    const int N = in_sizes[0] / (3 * B);

    reduce_kernel<<<B, 256>>>(cors, src, N);
    solve_kernel<<<(B + 31) / 32, 32>>>(out, N, B);
}

// round 7
// speedup vs baseline: 8.2666x; 1.0689x over previous
#include <cuda_runtime.h>
#include <math.h>

// Two-phase Kabsch / Procrustes.
//
// Kernel A: one CTA per batch, 256 threads; 6x LDG.128 streaming loads per
//   thread, 15 accumulators, warp shuffle reduce, then a cheap cross-warp
//   smem combine (one __syncthreads, threads 0..14 finish) -> ONE 15-float
//   record per batch, stored SoA (g_scr[k*BMAX+b]) for coalesced phase-B reads.
//
// Kernel B: one thread per batch; 15 coalesced L2-hot loads, forms H, runs a
//   6-iter fp32 scaled-Newton polar iteration (W = u@vh), emits
//   [[W^T, t],[0 0 0 1]].

#define BMAX 8192
__device__ float g_scr[15 * BMAX];   // SoA: [k][batch]

__global__ __launch_bounds__(256, 5)
void reduce_kernel(const float* __restrict__ cors,
                   const float* __restrict__ src,
                   int N)
{
    const int b    = blockIdx.x;
    const int tid  = threadIdx.x;
    const int lane = tid & 31;
    const int wid  = tid >> 5;
    const size_t base = (size_t)b * N * 3;

    const float4* __restrict__ s4 = reinterpret_cast<const float4*>(src + base);
    const float4* __restrict__ c4 = reinterpret_cast<const float4*>(cors + base);

    float acc[15];
    #pragma unroll
    for (int k = 0; k < 15; ++k) acc[k] = 0.f;
    // acc: [0..2] src sums, [3..5] pred sums, [6..14] H row-major

    const int nf4 = (N * 3) / 4;   // 768 for N=1024 -> one pass at 256 threads
    for (int f = tid * 3; f + 2 < nf4; f += blockDim.x * 3) {
        float a[12], c[12];
        float4 v;
        v = __ldcs(&s4[f + 0]); a[0] = v.x; a[1] = v.y; a[2]  = v.z; a[3]  = v.w;
        v = __ldcs(&s4[f + 1]); a[4] = v.x; a[5] = v.y; a[6]  = v.z; a[7]  = v.w;
        v = __ldcs(&s4[f + 2]); a[8] = v.x; a[9] = v.y; a[10] = v.z; a[11] = v.w;
        v = __ldcs(&c4[f + 0]); c[0] = v.x; c[1] = v.y; c[2]  = v.z; c[3]  = v.w;
        v = __ldcs(&c4[f + 1]); c[4] = v.x; c[5] = v.y; c[6]  = v.z; c[7]  = v.w;
        v = __ldcs(&c4[f + 2]); c[8] = v.x; c[9] = v.y; c[10] = v.z; c[11] = v.w;

        #pragma unroll
        for (int p = 0; p < 4; ++p) {
            const float sx = a[3*p + 0], sy = a[3*p + 1], sz = a[3*p + 2];
            const float px = sx + c[3*p + 0];
            const float py = sy + c[3*p + 1];
            const float pz = sz + c[3*p + 2];
            acc[0] += sx; acc[1] += sy; acc[2] += sz;
            acc[3] += px; acc[4] += py; acc[5] += pz;
            acc[6]  = fmaf(sx, px, acc[6]);  acc[7]  = fmaf(sx, py, acc[7]);  acc[8]  = fmaf(sx, pz, acc[8]);
            acc[9]  = fmaf(sy, px, acc[9]);  acc[10] = fmaf(sy, py, acc[10]); acc[11] = fmaf(sy, pz, acc[11]);
            acc[12] = fmaf(sz, px, acc[12]); acc[13] = fmaf(sz, py, acc[13]); acc[14] = fmaf(sz, pz, acc[14]);
        }
    }

    // per-warp shuffle reduction of the 15 accumulators
    #pragma unroll
    for (int off = 16; off > 0; off >>= 1) {
        #pragma unroll
        for (int k = 0; k < 15; ++k)
            acc[k] += __shfl_down_sync(0xFFFFFFFFu, acc[k], off);
    }

    // cross-warp combine: 8 warps x 15 values (padded row 16), threads 0..14 finish
    __shared__ float s_part[8][16];
    if (lane == 0) {
        #pragma unroll
        for (int k = 0; k < 15; ++k) s_part[wid][k] = acc[k];
    }
    __syncthreads();

    if (tid < 15) {
        float s = s_part[0][tid];
        #pragma unroll
        for (int w = 1; w < 8; ++w) s += s_part[w][tid];
        g_scr[tid * BMAX + b] = s;   // SoA: coalesced reads in kernel B
    }
}

// One thread per batch, 32-thread blocks spread across SMs.
__global__ __launch_bounds__(32)
void solve_kernel(float* __restrict__ out, int N, int B)
{
    const int b = blockIdx.x * blockDim.x + threadIdx.x;
    if (b >= B) return;

    float a[15];
    #pragma unroll
    for (int k = 0; k < 15; ++k) a[k] = __ldg(&g_scr[k * BMAX + b]);

    const float iN = 1.0f / (float)N;
    const float cs[3] = { a[0]*iN, a[1]*iN, a[2]*iN };   // src centroid
    const float cp[3] = { a[3]*iN, a[4]*iN, a[5]*iN };   // pred centroid

    // H[i][j] = sum(src_i * pred_j) - N * cs_i * cp_j
    float X[9];
    #pragma unroll
    for (int i = 0; i < 3; ++i)
        #pragma unroll
        for (int j = 0; j < 3; ++j)
            X[i*3 + j] = a[6 + i*3 + j] - (float)N * cs[i] * cp[j];

    // Scaled Newton iteration -> orthogonal polar factor W = u@vh
    #pragma unroll 1
    for (int it = 0; it < 6; ++it) {
        const float C0 =  (X[4]*X[8] - X[5]*X[7]);
        const float C1 = -(X[3]*X[8] - X[5]*X[6]);
        const float C2 =  (X[3]*X[7] - X[4]*X[6]);
        const float C3 = -(X[1]*X[8] - X[2]*X[7]);
        const float C4 =  (X[0]*X[8] - X[2]*X[6]);
        const float C5 = -(X[0]*X[7] - X[1]*X[6]);
        const float C6 =  (X[1]*X[5] - X[2]*X[4]);
        const float C7 = -(X[0]*X[5] - X[2]*X[3]);
        const float C8 =  (X[0]*X[4] - X[1]*X[3]);
        const float det    = X[0]*C0 + X[1]*C1 + X[2]*C2;
        const float invdet = __fdividef(1.0f, det);

        float XiT[9] = { C0*invdet, C1*invdet, C2*invdet,
                         C3*invdet, C4*invdet, C5*invdet,
                         C6*invdet, C7*invdet, C8*invdet };

        float nX = 0.f, nI = 0.f;
        #pragma unroll
        for (int k = 0; k < 9; ++k) { nX += X[k]*X[k]; nI += XiT[k]*XiT[k]; }

        // Higham Frobenius scaling: mu = (||X^-1||_F / ||X||_F)^(1/2)
        const float mu  = sqrtf(sqrtf(__fdividef(nI, nX)));
        const float imu = sqrtf(sqrtf(__fdividef(nX, nI)));

        #pragma unroll
        for (int k = 0; k < 9; ++k)
            X[k] = 0.5f * (mu * X[k] + imu * XiT[k]);
    }

    // r = W^T ; t = c_pred - r * c_src
    const float r00 = X[0], r01 = X[3], r02 = X[6];
    const float r10 = X[1], r11 = X[4], r12 = X[7];
    const float r20 = X[2], r21 = X[5], r22 = X[8];

    const float t0 = cp[0] - (r00*cs[0] + r01*cs[1] + r02*cs[2]);
    const float t1 = cp[1] - (r10*cs[0] + r11*cs[1] + r12*cs[2]);
    const float t2 = cp[2] - (r20*cs[0] + r21*cs[1] + r22*cs[2]);

    float4* o4 = reinterpret_cast<float4*>(out + (size_t)b * 16);
    o4[0] = make_float4(r00, r01, r02, t0);
    o4[1] = make_float4(r10, r11, r12, t1);
    o4[2] = make_float4(r20, r21, r22, t2);
    o4[3] = make_float4(0.f, 0.f, 0.f, 1.f);
}

extern "C" void kernel_launch(void* const* d_in, const int* in_sizes, int n_in,
                              void* d_out, int out_size)
{
    const float* cors = (const float*)d_in[0];
    const float* src  = (const float*)d_in[1];
    float* out        = (float*)d_out;

    const int B = out_size / 16;
    const int N = in_sizes[0] / (3 * B);

    reduce_kernel<<<B, 256>>>(cors, src, N);
    solve_kernel<<<(B + 31) / 32, 32>>>(out, N, B);
}

// round 8
// speedup vs baseline: 8.2771x; 1.0013x over previous
#include <cuda_runtime.h>
#include <math.h>

// Two-phase Kabsch / Procrustes with PDL overlap.
//
// Kernel A: one CTA per batch, 256 threads; 6x LDG.128 streaming loads per
//   thread, 15 accumulators, warp shuffle reduce, cross-warp smem combine ->
//   ONE 15-float record per batch, SoA (g_scr[k*BMAX+b]). Each CTA then
//   issues griddepcontrol.launch_dependents so the solve grid can launch
//   while A drains.
//
// Kernel B: launched with ProgrammaticStreamSerialization; opens with
//   griddepcontrol.wait, then one thread per batch forms H and runs a 5-iter
//   fp32 scaled-Newton polar iteration (W = u@vh), emits [[W^T, t],[0 0 0 1]].

#define BMAX 8192
__device__ float g_scr[15 * BMAX];   // SoA: [k][batch]

__global__ __launch_bounds__(256, 5)
void reduce_kernel(const float* __restrict__ cors,
                   const float* __restrict__ src,
                   int N)
{
    const int b    = blockIdx.x;
    const int tid  = threadIdx.x;
    const int lane = tid & 31;
    const int wid  = tid >> 5;
    const size_t base = (size_t)b * N * 3;

    const float4* __restrict__ s4 = reinterpret_cast<const float4*>(src + base);
    const float4* __restrict__ c4 = reinterpret_cast<const float4*>(cors + base);

    float acc[15];
    #pragma unroll
    for (int k = 0; k < 15; ++k) acc[k] = 0.f;
    // acc: [0..2] src sums, [3..5] pred sums, [6..14] H row-major

    const int nf4 = (N * 3) / 4;   // 768 for N=1024 -> one pass at 256 threads
    for (int f = tid * 3; f + 2 < nf4; f += blockDim.x * 3) {
        float a[12], c[12];
        float4 v;
        v = __ldcs(&s4[f + 0]); a[0] = v.x; a[1] = v.y; a[2]  = v.z; a[3]  = v.w;
        v = __ldcs(&s4[f + 1]); a[4] = v.x; a[5] = v.y; a[6]  = v.z; a[7]  = v.w;
        v = __ldcs(&s4[f + 2]); a[8] = v.x; a[9] = v.y; a[10] = v.z; a[11] = v.w;
        v = __ldcs(&c4[f + 0]); c[0] = v.x; c[1] = v.y; c[2]  = v.z; c[3]  = v.w;
        v = __ldcs(&c4[f + 1]); c[4] = v.x; c[5] = v.y; c[6]  = v.z; c[7]  = v.w;
        v = __ldcs(&c4[f + 2]); c[8] = v.x; c[9] = v.y; c[10] = v.z; c[11] = v.w;

        #pragma unroll
        for (int p = 0; p < 4; ++p) {
            const float sx = a[3*p + 0], sy = a[3*p + 1], sz = a[3*p + 2];
            const float px = sx + c[3*p + 0];
            const float py = sy + c[3*p + 1];
            const float pz = sz + c[3*p + 2];
            acc[0] += sx; acc[1] += sy; acc[2] += sz;
            acc[3] += px; acc[4] += py; acc[5] += pz;
            acc[6]  = fmaf(sx, px, acc[6]);  acc[7]  = fmaf(sx, py, acc[7]);  acc[8]  = fmaf(sx, pz, acc[8]);
            acc[9]  = fmaf(sy, px, acc[9]);  acc[10] = fmaf(sy, py, acc[10]); acc[11] = fmaf(sy, pz, acc[11]);
            acc[12] = fmaf(sz, px, acc[12]); acc[13] = fmaf(sz, py, acc[13]); acc[14] = fmaf(sz, pz, acc[14]);
        }
    }

    // per-warp shuffle reduction of the 15 accumulators
    #pragma unroll
    for (int off = 16; off > 0; off >>= 1) {
        #pragma unroll
        for (int k = 0; k < 15; ++k)
            acc[k] += __shfl_down_sync(0xFFFFFFFFu, acc[k], off);
    }

    // cross-warp combine: 8 warps x 15 values (padded row 16), threads 0..14 finish
    __shared__ float s_part[8][16];
    if (lane == 0) {
        #pragma unroll
        for (int k = 0; k < 15; ++k) s_part[wid][k] = acc[k];
    }
    __syncthreads();

    if (tid < 15) {
        float s = s_part[0][tid];
        #pragma unroll
        for (int w = 1; w < 8; ++w) s += s_part[w][tid];
        g_scr[tid * BMAX + b] = s;   // SoA: coalesced reads in kernel B
    }
    __syncthreads();

    // allow the dependent (solve) grid to launch; record writes above are
    // made visible to its griddepcontrol.wait
    if (tid == 0)
        asm volatile("griddepcontrol.launch_dependents;");
}

// One thread per batch, 32-thread blocks spread across SMs.
__global__ __launch_bounds__(32)
void solve_kernel(float* __restrict__ out, int N, int B)
{
    // park until the reduce grid's records are visible
    asm volatile("griddepcontrol.wait;" ::: "memory");

    const int b = blockIdx.x * blockDim.x + threadIdx.x;
    if (b >= B) return;

    float a[15];
    #pragma unroll
    for (int k = 0; k < 15; ++k) a[k] = __ldg(&g_scr[k * BMAX + b]);

    const float iN = 1.0f / (float)N;
    const float cs[3] = { a[0]*iN, a[1]*iN, a[2]*iN };   // src centroid
    const float cp[3] = { a[3]*iN, a[4]*iN, a[5]*iN };   // pred centroid

    // H[i][j] = sum(src_i * pred_j) - N * cs_i * cp_j
    float X[9];
    #pragma unroll
    for (int i = 0; i < 3; ++i)
        #pragma unroll
        for (int j = 0; j < 3; ++j)
            X[i*3 + j] = a[6 + i*3 + j] - (float)N * cs[i] * cp[j];

    // Scaled Newton iteration -> orthogonal polar factor W = u@vh
    #pragma unroll 1
    for (int it = 0; it < 5; ++it) {
        const float C0 =  (X[4]*X[8] - X[5]*X[7]);
        const float C1 = -(X[3]*X[8] - X[5]*X[6]);
        const float C2 =  (X[3]*X[7] - X[4]*X[6]);
        const float C3 = -(X[1]*X[8] - X[2]*X[7]);
        const float C4 =  (X[0]*X[8] - X[2]*X[6]);
        const float C5 = -(X[0]*X[7] - X[1]*X[6]);
        const float C6 =  (X[1]*X[5] - X[2]*X[4]);
        const float C7 = -(X[0]*X[5] - X[2]*X[3]);
        const float C8 =  (X[0]*X[4] - X[1]*X[3]);
        const float det    = X[0]*C0 + X[1]*C1 + X[2]*C2;
        const float invdet = __fdividef(1.0f, det);

        float XiT[9] = { C0*invdet, C1*invdet, C2*invdet,
                         C3*invdet, C4*invdet, C5*invdet,
                         C6*invdet, C7*invdet, C8*invdet };

        float nX = 0.f, nI = 0.f;
        #pragma unroll
        for (int k = 0; k < 9; ++k) { nX += X[k]*X[k]; nI += XiT[k]*XiT[k]; }

        // Higham Frobenius scaling: mu = (||X^-1||_F / ||X||_F)^(1/2)
        const float mu  = sqrtf(sqrtf(__fdividef(nI, nX)));
        const float imu = sqrtf(sqrtf(__fdividef(nX, nI)));

        #pragma unroll
        for (int k = 0; k < 9; ++k)
            X[k] = 0.5f * (mu * X[k] + imu * XiT[k]);
    }

    // r = W^T ; t = c_pred - r * c_src
    const float r00 = X[0], r01 = X[3], r02 = X[6];
    const float r10 = X[1], r11 = X[4], r12 = X[7];
    const float r20 = X[2], r21 = X[5], r22 = X[8];

    const float t0 = cp[0] - (r00*cs[0] + r01*cs[1] + r02*cs[2]);
    const float t1 = cp[1] - (r10*cs[0] + r11*cs[1] + r12*cs[2]);
    const float t2 = cp[2] - (r20*cs[0] + r21*cs[1] + r22*cs[2]);

    float4* o4 = reinterpret_cast<float4*>(out + (size_t)b * 16);
    o4[0] = make_float4(r00, r01, r02, t0);
    o4[1] = make_float4(r10, r11, r12, t1);
    o4[2] = make_float4(r20, r21, r22, t2);
    o4[3] = make_float4(0.f, 0.f, 0.f, 1.f);
}

extern "C" void kernel_launch(void* const* d_in, const int* in_sizes, int n_in,
                              void* d_out, int out_size)
{
    const float* cors = (const float*)d_in[0];
    const float* src  = (const float*)d_in[1];
    float* out        = (float*)d_out;

    const int B = out_size / 16;
    const int N = in_sizes[0] / (3 * B);

    reduce_kernel<<<B, 256>>>(cors, src, N);

    // Programmatic dependent launch: solve launches while reduce drains,
    // parked on griddepcontrol.wait.
    cudaLaunchConfig_t cfg = {};
    cfg.gridDim  = dim3((B + 31) / 32, 1, 1);
    cfg.blockDim = dim3(32, 1, 1);
    cfg.stream   = 0;
    cudaLaunchAttribute attrs[1];
    attrs[0].id = cudaLaunchAttributeProgrammaticStreamSerialization;
    attrs[0].val.programmaticStreamSerializationAllowed = 1;
    cfg.attrs    = attrs;
    cfg.numAttrs = 1;
    cudaLaunchKernelEx(&cfg, solve_kernel, out, N, B);
}